// round 6
// baseline (speedup 1.0000x reference)
#include <cuda_runtime.h>

// WaveletLayer fused: db2 DWT -> scale -> inverse DWT -> ReLU, fully collapsed.
//
// QMF identity (hi[i] = (-1)^i lo[3-i]) collapses the whole chain to, per
// input pair (u,v) = (x[2m], x[2m+1]), with t = sqrt(3)/4:
//   p = 0.75u - t*v,  q = u - p
//   r = 0.25v - t*u,  s = v - r
//   out[2m]   = relu(k[m]*p + k[m+1]*q)
//   out[2m+1] = relu(k[m]*r + k[m+1]*s)
// Boundary/padding terms cancel identically.
//
// R6: each thread handles the same 8-col window of TWO adjacent rows.
// 8 independent LDG.128 issued up front (4 x, 4 kern) -> 2x outstanding
// bytes per warp vs R5. Row pair (2y, 2y+1) => K misalignment pair (d, d+1),
// d in {0,2}: single 2-way uniform branch.

#define NCOL 4096
#define LOUT 2049
#define NT   256

__device__ __forceinline__ void wave_pairs(
    float4 X0, float4 X1,
    float k0, float k1, float k2, float k3, float k4,
    float4& r0, float4& r1)
{
    const float T = 0.43301270189221932f;  // sqrt(3)/4

    float u, v, p, q, rr, ss;

    u = X0.x; v = X0.y;
    p = fmaf(-T, v, 0.75f * u); q = u - p;
    rr = fmaf(-T, u, 0.25f * v); ss = v - rr;
    r0.x = fmaxf(fmaf(k1, q,  k0 * p),  0.0f);
    r0.y = fmaxf(fmaf(k1, ss, k0 * rr), 0.0f);

    u = X0.z; v = X0.w;
    p = fmaf(-T, v, 0.75f * u); q = u - p;
    rr = fmaf(-T, u, 0.25f * v); ss = v - rr;
    r0.z = fmaxf(fmaf(k2, q,  k1 * p),  0.0f);
    r0.w = fmaxf(fmaf(k2, ss, k1 * rr), 0.0f);

    u = X1.x; v = X1.y;
    p = fmaf(-T, v, 0.75f * u); q = u - p;
    rr = fmaf(-T, u, 0.25f * v); ss = v - rr;
    r1.x = fmaxf(fmaf(k3, q,  k2 * p),  0.0f);
    r1.y = fmaxf(fmaf(k3, ss, k2 * rr), 0.0f);

    u = X1.z; v = X1.w;
    p = fmaf(-T, v, 0.75f * u); q = u - p;
    rr = fmaf(-T, u, 0.25f * v); ss = v - rr;
    r1.z = fmaxf(fmaf(k4, q,  k3 * p),  0.0f);
    r1.w = fmaxf(fmaf(k4, ss, k3 * rr), 0.0f);
}

__global__ __launch_bounds__(NT) void wavelet_fused_kernel(
    const float* __restrict__ x,
    const float* __restrict__ kern,
    float* __restrict__ out)
{
    const int row0 = blockIdx.y * 2;                        // even row
    const int m0   = (blockIdx.x * NT + threadIdx.x) * 4;   // first pair index
    const int base = 2 * m0;                                // first output col

    // ---- issue all 8 loads up front (max MLP) ----
    const size_t offa = (size_t)row0 * NCOL + base;
    const float4* xa = reinterpret_cast<const float4*>(x + offa);
    const float4* xb = reinterpret_cast<const float4*>(x + offa + NCOL);
    float4 Xa0 = xa[0];
    float4 Xa1 = xa[1];
    float4 Xb0 = xb[0];
    float4 Xb1 = xb[1];

    const int wa = LOUT * row0 + m0;
    const int da = wa & 3;                 // in {0, 2}, uniform per block
    const int wb = wa + LOUT;
    const int db = da + 1;                 // in {1, 3}
    const float4* kpa = reinterpret_cast<const float4*>(kern + (wa - da));
    const float4* kpb = reinterpret_cast<const float4*>(kern + (wb - db));
    float4 fa0 = kpa[0];
    float4 fa1 = kpa[1];
    float4 fb0 = kpb[0];
    float4 fb1 = kpb[1];

    // ---- uniform 2-way select of the two K windows ----
    float ka0, ka1, ka2, ka3, ka4;
    float kb0, kb1, kb2, kb3, kb4;
    if (da == 0) {
        ka0 = fa0.x; ka1 = fa0.y; ka2 = fa0.z; ka3 = fa0.w; ka4 = fa1.x;
        kb0 = fb0.y; kb1 = fb0.z; kb2 = fb0.w; kb3 = fb1.x; kb4 = fb1.y;
    } else {  // da == 2
        ka0 = fa0.z; ka1 = fa0.w; ka2 = fa1.x; ka3 = fa1.y; ka4 = fa1.z;
        kb0 = fb0.w; kb1 = fb1.x; kb2 = fb1.y; kb3 = fb1.z; kb4 = fb1.w;
    }

    float4 ra0, ra1, rb0, rb1;
    wave_pairs(Xa0, Xa1, ka0, ka1, ka2, ka3, ka4, ra0, ra1);
    wave_pairs(Xb0, Xb1, kb0, kb1, kb2, kb3, kb4, rb0, rb1);

    float4* oa = reinterpret_cast<float4*>(out + offa);
    float4* ob = reinterpret_cast<float4*>(out + offa + NCOL);
    __stcs(oa,     ra0);
    __stcs(oa + 1, ra1);
    __stcs(ob,     rb0);
    __stcs(ob + 1, rb1);
}

extern "C" void kernel_launch(void* const* d_in, const int* in_sizes, int n_in,
                              void* d_out, int out_size)
{
    const float* x    = (const float*)d_in[0];
    const float* kern = (const float*)d_in[1];
    float*       out  = (float*)d_out;

    dim3 grid(2, 2048);   // x: 2 blocks x 256 thr x 4 pairs = 2048 pairs/row
                          // y: 2048 row-pairs
    wavelet_fused_kernel<<<grid, NT>>>(x, kern, out);
}